// round 5
// baseline (speedup 1.0000x reference)
#include <cuda_runtime.h>
#include <math.h>

#define NB 4
#define NS 2048
#define ND 1024
#define NH 16
#define NDH 64
#define NM (NB * NS)   // 8192

// Scratch (static device globals: allocation-free per harness rules)
__device__ float g_Q[NB * NH * NS * NDH];   // 32 MB, [b,h,s,dh]
__device__ float g_K[NB * NH * NS * NDH];
__device__ float g_V[NB * NH * NS * NDH];
__device__ float g_O[(size_t)NM * ND];      // attention output, [b,s,h*dh+d]

// ---------------------------------------------------------------------------
// GEMM: C[M,N] = A[M,K] * W[N,K]^T   (both operands K-contiguous)
// 128x128 tile, BK=16, 256 threads, 8x8 per thread, smem stored transposed
// MODE 0: A = x, W = W_qkv viewed [3072,1024]; scatter into g_Q/g_K/g_V
// MODE 1: A = g_O, W = W_o [1024,1024]; write C = final output
// ---------------------------------------------------------------------------
template <int MODE>
__global__ __launch_bounds__(256) void gemm_kernel(const float* __restrict__ A,
                                                   const float* __restrict__ W,
                                                   float* __restrict__ C) {
    constexpr int K = 1024;
    __shared__ float As[16][128];
    __shared__ float Bs[16][128];
    const int tid = threadIdx.x;
    const int tx = tid & 15, ty = tid >> 4;
    const int m0 = blockIdx.y * 128, n0 = blockIdx.x * 128;
    const float* Ap = ((MODE == 1) ? (const float*)g_O : A) + (size_t)m0 * K;
    const float* Wp = W + (size_t)n0 * K;

    float acc[8][8] = {};
    for (int k0 = 0; k0 < K; k0 += 16) {
#pragma unroll
        for (int t = 0; t < 2; t++) {
            int f = (tid << 1) + t;        // 0..511 float4 slots
            int row = f >> 2;              // 0..127
            int c0 = (f & 3) << 2;         // 0,4,8,12
            float4 av = *(const float4*)(Ap + (size_t)row * K + k0 + c0);
            As[c0 + 0][row] = av.x; As[c0 + 1][row] = av.y;
            As[c0 + 2][row] = av.z; As[c0 + 3][row] = av.w;
            float4 wv = *(const float4*)(Wp + (size_t)row * K + k0 + c0);
            Bs[c0 + 0][row] = wv.x; Bs[c0 + 1][row] = wv.y;
            Bs[c0 + 2][row] = wv.z; Bs[c0 + 3][row] = wv.w;
        }
        __syncthreads();
#pragma unroll
        for (int kk = 0; kk < 16; kk++) {
            float a[8], b[8];
            *(float4*)(a)     = *(const float4*)&As[kk][ty * 8];
            *(float4*)(a + 4) = *(const float4*)&As[kk][ty * 8 + 4];
            *(float4*)(b)     = *(const float4*)&Bs[kk][tx * 8];
            *(float4*)(b + 4) = *(const float4*)&Bs[kk][tx * 8 + 4];
#pragma unroll
            for (int i = 0; i < 8; i++)
#pragma unroll
                for (int j = 0; j < 8; j++)
                    acc[i][j] = fmaf(a[i], b[j], acc[i][j]);
        }
        __syncthreads();
    }

    if (MODE == 0) {
        // n = n0 + tx*8 .. +7: stays within one qkv slab and one head (8 | 64)
        int nb = n0 + tx * 8;
        int kk_ = nb >> 10;
        int o = nb & 1023;
        int h = o >> 6, dd = o & 63;
        float* base = (kk_ == 0) ? g_Q : ((kk_ == 1) ? g_K : g_V);
#pragma unroll
        for (int i = 0; i < 8; i++) {
            int m = m0 + ty * 8 + i;
            int b = m >> 11, s = m & (NS - 1);
            float* dst = base + ((size_t)((b * NH + h) * NS + s) << 6) + dd;
            *(float4*)dst       = make_float4(acc[i][0], acc[i][1], acc[i][2], acc[i][3]);
            *(float4*)(dst + 4) = make_float4(acc[i][4], acc[i][5], acc[i][6], acc[i][7]);
        }
    } else {
#pragma unroll
        for (int i = 0; i < 8; i++) {
            int m = m0 + ty * 8 + i;
            float* dst = C + (size_t)m * 1024 + n0 + tx * 8;
            *(float4*)dst       = make_float4(acc[i][0], acc[i][1], acc[i][2], acc[i][3]);
            *(float4*)(dst + 4) = make_float4(acc[i][4], acc[i][5], acc[i][6], acc[i][7]);
        }
    }
}

// ---------------------------------------------------------------------------
// RoPE applied in-place to g_Q and g_K. One thread per (b,h,s,pair i).
// pairs interleaved: (2i, 2i+1), inv_freq = theta^(-i/32), dh=64.
// ---------------------------------------------------------------------------
__global__ __launch_bounds__(256) void rope_kernel(const int* __restrict__ pos) {
    int idx = blockIdx.x * 256 + threadIdx.x;        // exact: 4M threads
    int i = idx & 31;
    int s = (idx >> 5) & (NS - 1);
    float p = (float)pos[s];
    float invf = powf(10000.0f, -(float)i * (1.0f / 32.0f));
    float ang = p * invf;
    float sn, cs;
    sincosf(ang, &sn, &cs);
    float2* q = (float2*)g_Q + idx;
    float2 qv = *q;
    *q = make_float2(qv.x * cs - qv.y * sn, qv.x * sn + qv.y * cs);
    float2* k = (float2*)g_K + idx;
    float2 kv = *k;
    *k = make_float2(kv.x * cs - kv.y * sn, kv.x * sn + kv.y * cs);
}

// ---------------------------------------------------------------------------
// Flash attention, fp32. One CTA per (b*h, 64-query block). 256 threads as
// a 16x16 grid, 4x4 register tiles for both S=QK^T and O+=P*V.
// Causal: only kb <= qb tiles computed; diagonal tile masked.
// smem: q[d][i], k[d][j] (transposed for float4 LDS), v[j][d];
// p[i][j] aliases the k tile (k is dead once S is computed).
// ---------------------------------------------------------------------------
__global__ __launch_bounds__(256) void attn_kernel() {
    extern __shared__ float sm[];
    float* q_s = sm;          // 64*64
    float* k_s = sm + 4096;   // 64*64 (reused as p)
    float* v_s = sm + 8192;   // 64*64
    const int tid = threadIdx.x;
    const int tx = tid & 15, ty = tid >> 4;
    const int qb = gridDim.x - 1 - blockIdx.x;   // big blocks first (load balance)
    const int bh = blockIdx.y;
    const float* Qp = g_Q + (size_t)bh * NS * NDH;
    const float* Kp = g_K + (size_t)bh * NS * NDH;
    const float* Vp = g_V + (size_t)bh * NS * NDH;

    const int lrow = tid & 63;           // loader: row handled by this thread
    const int ld0 = (tid >> 6) * 16;     // loader: 16-wide d-slice
    {   // load q transposed, pre-scaled by 1/sqrt(64)
        const float* src = Qp + (size_t)(qb * 64 + lrow) * 64 + ld0;
#pragma unroll
        for (int t = 0; t < 4; t++) {
            float4 v = *(const float4*)(src + t * 4);
            int d = ld0 + t * 4;
            q_s[(d + 0) * 64 + lrow] = v.x * 0.125f;
            q_s[(d + 1) * 64 + lrow] = v.y * 0.125f;
            q_s[(d + 2) * 64 + lrow] = v.z * 0.125f;
            q_s[(d + 3) * 64 + lrow] = v.w * 0.125f;
        }
    }

    float acc[4][4] = {};
    float mrow[4] = {-INFINITY, -INFINITY, -INFINITY, -INFINITY};
    float lsum[4] = {};   // per-thread partial row sums (consistently scaled)

    const int nkb = qb + 1;
    for (int kb = 0; kb < nkb; kb++) {
        __syncthreads();   // p/v from previous iter fully consumed
        {   // load k (transposed) and v (natural)
            const float* ks = Kp + (size_t)(kb * 64 + lrow) * 64 + ld0;
            const float* vs = Vp + (size_t)(kb * 64 + lrow) * 64 + ld0;
#pragma unroll
            for (int t = 0; t < 4; t++) {
                float4 kv = *(const float4*)(ks + t * 4);
                int d = ld0 + t * 4;
                k_s[(d + 0) * 64 + lrow] = kv.x;
                k_s[(d + 1) * 64 + lrow] = kv.y;
                k_s[(d + 2) * 64 + lrow] = kv.z;
                k_s[(d + 3) * 64 + lrow] = kv.w;
                *(float4*)&v_s[lrow * 64 + d] = *(const float4*)(vs + t * 4);
            }
        }
        __syncthreads();

        // S = Q * K^T  (4x4 per thread; rows 4ty+r, cols 4tx+c)
        float sc[4][4] = {};
#pragma unroll 8
        for (int d = 0; d < 64; d++) {
            float4 aq = *(const float4*)&q_s[d * 64 + ty * 4];
            float4 ak = *(const float4*)&k_s[d * 64 + tx * 4];
            float a4[4] = {aq.x, aq.y, aq.z, aq.w};
            float b4[4] = {ak.x, ak.y, ak.z, ak.w};
#pragma unroll
            for (int r = 0; r < 4; r++)
#pragma unroll
                for (int c = 0; c < 4; c++)
                    sc[r][c] = fmaf(a4[r], b4[c], sc[r][c]);
        }
        __syncthreads();          // k tile dead; its smem becomes the p tile
        float* p_s = k_s;

        const bool diag = (kb == qb);
#pragma unroll
        for (int r = 0; r < 4; r++) {
            if (diag) {
#pragma unroll
                for (int c = 0; c < 4; c++)
                    if (4 * tx + c > 4 * ty + r) sc[r][c] = -INFINITY;
            }
            // row max across the 16 tx-lanes (butterfly stays in 16-lane half)
            float mx = fmaxf(fmaxf(sc[r][0], sc[r][1]), fmaxf(sc[r][2], sc[r][3]));
#pragma unroll
            for (int o = 8; o > 0; o >>= 1)
                mx = fmaxf(mx, __shfl_xor_sync(0xffffffffu, mx, o));
            float mnew = fmaxf(mrow[r], mx);
            float alpha = expf(mrow[r] - mnew);
            mrow[r] = mnew;
            float rs = 0.f;
#pragma unroll
            for (int c = 0; c < 4; c++) {
                float pv = expf(sc[r][c] - mnew);
                sc[r][c] = pv;
                rs += pv;
            }
            lsum[r] = lsum[r] * alpha + rs;
#pragma unroll
            for (int c = 0; c < 4; c++) acc[r][c] *= alpha;
            *(float4*)&p_s[(4 * ty + r) * 64 + 4 * tx] =
                make_float4(sc[r][0], sc[r][1], sc[r][2], sc[r][3]);
        }
        __syncthreads();

        // O += P * V (acc cols are d = 4tx+c)
#pragma unroll 8
        for (int j = 0; j < 64; j++) {
            float4 vv = *(const float4*)&v_s[j * 64 + tx * 4];
#pragma unroll
            for (int r = 0; r < 4; r++) {
                float pj = p_s[(4 * ty + r) * 64 + j];
                acc[r][0] = fmaf(pj, vv.x, acc[r][0]);
                acc[r][1] = fmaf(pj, vv.y, acc[r][1]);
                acc[r][2] = fmaf(pj, vv.z, acc[r][2]);
                acc[r][3] = fmaf(pj, vv.w, acc[r][3]);
            }
        }
    }

    const int b = bh >> 4, h = bh & 15;
#pragma unroll
    for (int r = 0; r < 4; r++) {
        float l = lsum[r];
#pragma unroll
        for (int o = 8; o > 0; o >>= 1)
            l += __shfl_xor_sync(0xffffffffu, l, o);
        float inv = 1.0f / l;
        int srow = qb * 64 + 4 * ty + r;
        float* dst = g_O + (size_t)(b * NS + srow) * ND + h * 64 + 4 * tx;
        *(float4*)dst = make_float4(acc[r][0] * inv, acc[r][1] * inv,
                                    acc[r][2] * inv, acc[r][3] * inv);
    }
}

// ---------------------------------------------------------------------------
extern "C" void kernel_launch(void* const* d_in, const int* in_sizes, int n_in,
                              void* d_out, int out_size) {
    (void)in_sizes; (void)n_in; (void)out_size;
    const float* x     = (const float*)d_in[0];   // [4,2048,1024]
    const float* W_qkv = (const float*)d_in[1];   // [3,1024,1024] (o,d K-major)
    const float* W_o   = (const float*)d_in[2];   // [1024,1024]
    const int*   pos   = (const int*)d_in[3];     // [2048]
    float* out = (float*)d_out;

    cudaFuncSetAttribute(attn_kernel,
                         cudaFuncAttributeMaxDynamicSharedMemorySize, 49152);

    // 1) fused QKV projection -> scatter to [b,h,s,dh]
    gemm_kernel<0><<<dim3(3072 / 128, NM / 128), 256>>>(x, W_qkv, nullptr);
    // 2) RoPE in-place on Q and K
    rope_kernel<<<(NB * NH * NS * 32) / 256, 256>>>(pos);
    // 3) causal flash attention -> g_O in [b,s,D] layout
    attn_kernel<<<dim3(NS / 64, NB * NH), 256, 49152>>>();
    // 4) output projection
    gemm_kernel<1><<<dim3(ND / 128, NM / 128), 256>>>(nullptr, W_o, out);
}

// round 9
// speedup vs baseline: 1.4927x; 1.4927x over previous
#include <cuda_runtime.h>
#include <cuda_bf16.h>
#include <math.h>
#include <stdint.h>

#define NB 4
#define NS 2048
#define ND 1024
#define NH 16
#define NDH 64
#define NM (NB * NS)   // 8192

// Scratch (static device globals: allocation-free per harness rules)
__device__ float g_Q[NB * NH * NS * NDH];   // 32 MB, [b,h,s,dh]
__device__ float g_K[NB * NH * NS * NDH];
__device__ float g_V[NB * NH * NS * NDH];
__device__ float g_O[(size_t)NM * ND];      // attention output, [b,s,h*dh+d]

// ===========================================================================
// Helpers
// ===========================================================================
__device__ __forceinline__ uint32_t smem_to_u32(const void* p) {
    uint32_t a;
    asm("{ .reg .u64 t; cvta.to.shared.u64 t, %1; cvt.u32.u64 %0, t; }"
        : "=r"(a) : "l"(p));
    return a;
}
__device__ __forceinline__ uint32_t lds32(uint32_t addr) {
    uint32_t v;
    asm volatile("ld.shared.b32 %0, [%1];" : "=r"(v) : "r"(addr));
    return v;
}
__device__ __forceinline__ void sts64(uint32_t addr, uint2 v) {
    asm volatile("st.shared.v2.b32 [%0], {%1, %2};" :: "r"(addr), "r"(v.x), "r"(v.y)
                 : "memory");
}

// warp-level bf16 MMA: D(16x8,f32) += A(16x16,bf16 row) * B(16x8,bf16 col)
__device__ __forceinline__ void mma16816(float* c, const uint32_t* a, const uint32_t* b) {
    asm volatile(
        "mma.sync.aligned.m16n8k16.row.col.f32.bf16.bf16.f32 "
        "{%0,%1,%2,%3}, {%4,%5,%6,%7}, {%8,%9}, {%0,%1,%2,%3};"
        : "+f"(c[0]), "+f"(c[1]), "+f"(c[2]), "+f"(c[3])
        : "r"(a[0]), "r"(a[1]), "r"(a[2]), "r"(a[3]), "r"(b[0]), "r"(b[1]));
}

// fp32 -> (bf16 hi, bf16 lo) split of a float4 into packed bf16x2 words.
// Low half of each 32-bit word = lower-index element.
__device__ __forceinline__ void cvt_split4(float4 v, uint2& h, uint2& l) {
    uint32_t h01, h23, l01, l23;
    asm("cvt.rn.bf16x2.f32 %0, %1, %2;" : "=r"(h01) : "f"(v.y), "f"(v.x));
    asm("cvt.rn.bf16x2.f32 %0, %1, %2;" : "=r"(h23) : "f"(v.w), "f"(v.z));
    float r0 = v.x - __uint_as_float(h01 << 16);
    float r1 = v.y - __uint_as_float(h01 & 0xffff0000u);
    float r2 = v.z - __uint_as_float(h23 << 16);
    float r3 = v.w - __uint_as_float(h23 & 0xffff0000u);
    asm("cvt.rn.bf16x2.f32 %0, %1, %2;" : "=r"(l01) : "f"(r1), "f"(r0));
    asm("cvt.rn.bf16x2.f32 %0, %1, %2;" : "=r"(l23) : "f"(r3), "f"(r2));
    h = make_uint2(h01, h23);
    l = make_uint2(l01, l23);
}

// ===========================================================================
// HMMA GEMM: C[M,N] = A[M,K] * W[N,K]^T via bf16 3-term split (fp32-grade).
// 128x128 tile/CTA, K-tile 32, 256 threads (8 warps, 2x4 warp grid, 64x32/warp).
// Smem tiles stride 40 bf16 (80B): conflict-free fragment LDS (stride = 20 banks).
// MODE 0: A = x, W = W_qkv [3072,1024]; scatter to g_Q/g_K/g_V [b,h,s,dh]
// MODE 1: A = g_O, W = W_o [1024,1024]; C = final output
// ===========================================================================
#define SROW 80              // smem row stride in bytes (40 bf16)
#define TILE_B (128 * SROW)  // 10240 B per tile

template <int MODE>
__global__ __launch_bounds__(256) void gemm_mma(const float* __restrict__ A,
                                                const float* __restrict__ W,
                                                float* __restrict__ C) {
    constexpr int K = 1024;
    extern __shared__ char smem[];
    const uint32_t sb = smem_to_u32(smem);
    const uint32_t S_AH = sb;
    const uint32_t S_AL = sb + TILE_B;
    const uint32_t S_BH = sb + 2 * TILE_B;
    const uint32_t S_BL = sb + 3 * TILE_B;

    const int tid = threadIdx.x;
    const int wid = tid >> 5, lane = tid & 31;
    const int wm = wid & 1, wn = wid >> 1;   // warp tile: rows wm*64.., cols wn*32..
    const int lr = lane >> 2, lc = lane & 3;
    const int m0 = blockIdx.y * 128, n0 = blockIdx.x * 128;
    const float* Ap = ((MODE == 1) ? (const float*)g_O : A) + (size_t)m0 * K;
    const float* Wp = W + (size_t)n0 * K;

    float acc[4][4][4] = {};

    // per-thread fragment base offsets (bytes)
    const uint32_t pa = (uint32_t)((wm * 64 + lr) * SROW + lc * 4);
    const uint32_t pb = (uint32_t)((wn * 32 + lr) * SROW + lc * 4);

    for (int kt = 0; kt < K / 32; kt++) {
        float4 av[4], bv[4];
#pragma unroll
        for (int t = 0; t < 4; t++) {
            int idx = tid + t * 256;           // 0..1023
            int row = idx >> 3, c4 = idx & 7;  // 128 rows x 8 float4
            const float* a = Ap + (size_t)row * K + kt * 32 + c4 * 4;
            const float* w = Wp + (size_t)row * K + kt * 32 + c4 * 4;
            av[t] = *(const float4*)a;
            bv[t] = *(const float4*)w;
        }
        __syncthreads();   // previous tile fully consumed by all warps
#pragma unroll
        for (int t = 0; t < 4; t++) {
            int idx = tid + t * 256;
            int row = idx >> 3, c4 = idx & 7;
            uint32_t off = (uint32_t)(row * SROW + c4 * 8);
            uint2 h, l;
            cvt_split4(av[t], h, l);
            sts64(S_AH + off, h);
            sts64(S_AL + off, l);
            cvt_split4(bv[t], h, l);
            sts64(S_BH + off, h);
            sts64(S_BL + off, l);
        }
        __syncthreads();

#pragma unroll
        for (int ks = 0; ks < 2; ks++) {
            const uint32_t ko = ks * 32;   // 16 bf16 = 32 bytes
            uint32_t ah[4][4], al[4][4], bh[4][2], bl[4][2];
#pragma unroll
            for (int i = 0; i < 4; i++) {
                uint32_t p = pa + i * (16 * SROW) + ko;
                ah[i][0] = lds32(S_AH + p);
                ah[i][1] = lds32(S_AH + p + 8 * SROW);
                ah[i][2] = lds32(S_AH + p + 16);
                ah[i][3] = lds32(S_AH + p + 8 * SROW + 16);
                al[i][0] = lds32(S_AL + p);
                al[i][1] = lds32(S_AL + p + 8 * SROW);
                al[i][2] = lds32(S_AL + p + 16);
                al[i][3] = lds32(S_AL + p + 8 * SROW + 16);
            }
#pragma unroll
            for (int j = 0; j < 4; j++) {
                uint32_t p = pb + j * (8 * SROW) + ko;
                bh[j][0] = lds32(S_BH + p);
                bh[j][1] = lds32(S_BH + p + 16);
                bl[j][0] = lds32(S_BL + p);
                bl[j][1] = lds32(S_BL + p + 16);
            }
#pragma unroll
            for (int i = 0; i < 4; i++)
#pragma unroll
                for (int j = 0; j < 4; j++) {
                    mma16816(acc[i][j], ah[i], bh[j]);
                    mma16816(acc[i][j], ah[i], bl[j]);
                    mma16816(acc[i][j], al[i], bh[j]);
                }
        }
    }

    // Epilogue: thread owns rows (m_at, m_at+8), cols (n_at, n_at+1) per atom
#pragma unroll
    for (int i = 0; i < 4; i++) {
        int m = m0 + wm * 64 + i * 16 + lr;
#pragma unroll
        for (int j = 0; j < 4; j++) {
            int n = n0 + wn * 32 + j * 8 + lc * 2;
            if (MODE == 0) {
                int kk = n >> 10;
                int o = n & 1023;
                int h = o >> 6, dd = o & 63;
                float* base = (kk == 0) ? g_Q : ((kk == 1) ? g_K : g_V);
                int b = m >> 11, s = m & (NS - 1);
                float* d0 = base + ((size_t)((b * NH + h) * NS + s) << 6) + dd;
                *(float2*)d0 = make_float2(acc[i][j][0], acc[i][j][1]);
                float* d1 = d0 + (8 << 6);   // row m+8 (same b-block: 8 < 2048)
                *(float2*)d1 = make_float2(acc[i][j][2], acc[i][j][3]);
            } else {
                float* d0 = C + (size_t)m * ND + n;
                *(float2*)d0 = make_float2(acc[i][j][0], acc[i][j][1]);
                float* d1 = d0 + (size_t)8 * ND;
                *(float2*)d1 = make_float2(acc[i][j][2], acc[i][j][3]);
            }
        }
    }
}

// ---------------------------------------------------------------------------
// RoPE applied in-place to g_Q and g_K. One thread per (b,h,s,pair i).
// ---------------------------------------------------------------------------
__global__ __launch_bounds__(256) void rope_kernel(const int* __restrict__ pos) {
    int idx = blockIdx.x * 256 + threadIdx.x;
    int i = idx & 31;
    int s = (idx >> 5) & (NS - 1);
    float p = (float)pos[s];
    float invf = powf(10000.0f, -(float)i * (1.0f / 32.0f));
    float ang = p * invf;
    float sn, cs;
    sincosf(ang, &sn, &cs);
    float2* q = (float2*)g_Q + idx;
    float2 qv = *q;
    *q = make_float2(qv.x * cs - qv.y * sn, qv.x * sn + qv.y * cs);
    float2* k = (float2*)g_K + idx;
    float2 kv = *k;
    *k = make_float2(kv.x * cs - kv.y * sn, kv.x * sn + kv.y * cs);
}

// ---------------------------------------------------------------------------
// Flash attention, fp32 (unchanged: ~85% of fp32-FFMA roofline).
// ---------------------------------------------------------------------------
__global__ __launch_bounds__(256) void attn_kernel() {
    extern __shared__ float sm[];
    float* q_s = sm;          // 64*64
    float* k_s = sm + 4096;   // 64*64 (reused as p)
    float* v_s = sm + 8192;   // 64*64
    const int tid = threadIdx.x;
    const int tx = tid & 15, ty = tid >> 4;
    const int qb = gridDim.x - 1 - blockIdx.x;
    const int bh = blockIdx.y;
    const float* Qp = g_Q + (size_t)bh * NS * NDH;
    const float* Kp = g_K + (size_t)bh * NS * NDH;
    const float* Vp = g_V + (size_t)bh * NS * NDH;

    const int lrow = tid & 63;
    const int ld0 = (tid >> 6) * 16;
    {
        const float* src = Qp + (size_t)(qb * 64 + lrow) * 64 + ld0;
#pragma unroll
        for (int t = 0; t < 4; t++) {
            float4 v = *(const float4*)(src + t * 4);
            int d = ld0 + t * 4;
            q_s[(d + 0) * 64 + lrow] = v.x * 0.125f;
            q_s[(d + 1) * 64 + lrow] = v.y * 0.125f;
            q_s[(d + 2) * 64 + lrow] = v.z * 0.125f;
            q_s[(d + 3) * 64 + lrow] = v.w * 0.125f;
        }
    }

    float acc[4][4] = {};
    float mrow[4] = {-INFINITY, -INFINITY, -INFINITY, -INFINITY};
    float lsum[4] = {};

    const int nkb = qb + 1;
    for (int kb = 0; kb < nkb; kb++) {
        __syncthreads();
        {
            const float* ks = Kp + (size_t)(kb * 64 + lrow) * 64 + ld0;
            const float* vs = Vp + (size_t)(kb * 64 + lrow) * 64 + ld0;
#pragma unroll
            for (int t = 0; t < 4; t++) {
                float4 kv = *(const float4*)(ks + t * 4);
                int d = ld0 + t * 4;
                k_s[(d + 0) * 64 + lrow] = kv.x;
                k_s[(d + 1) * 64 + lrow] = kv.y;
                k_s[(d + 2) * 64 + lrow] = kv.z;
                k_s[(d + 3) * 64 + lrow] = kv.w;
                *(float4*)&v_s[lrow * 64 + d] = *(const float4*)(vs + t * 4);
            }
        }
        __syncthreads();

        float sc[4][4] = {};
#pragma unroll 8
        for (int d = 0; d < 64; d++) {
            float4 aq = *(const float4*)&q_s[d * 64 + ty * 4];
            float4 ak = *(const float4*)&k_s[d * 64 + tx * 4];
            float a4[4] = {aq.x, aq.y, aq.z, aq.w};
            float b4[4] = {ak.x, ak.y, ak.z, ak.w};
#pragma unroll
            for (int r = 0; r < 4; r++)
#pragma unroll
                for (int c = 0; c < 4; c++)
                    sc[r][c] = fmaf(a4[r], b4[c], sc[r][c]);
        }
        __syncthreads();
        float* p_s = k_s;

        const bool diag = (kb == qb);
#pragma unroll
        for (int r = 0; r < 4; r++) {
            if (diag) {
#pragma unroll
                for (int c = 0; c < 4; c++)
                    if (4 * tx + c > 4 * ty + r) sc[r][c] = -INFINITY;
            }
            float mx = fmaxf(fmaxf(sc[r][0], sc[r][1]), fmaxf(sc[r][2], sc[r][3]));
#pragma unroll
            for (int o = 8; o > 0; o >>= 1)
                mx = fmaxf(mx, __shfl_xor_sync(0xffffffffu, mx, o));
            float mnew = fmaxf(mrow[r], mx);
            float alpha = expf(mrow[r] - mnew);
            mrow[r] = mnew;
            float rs = 0.f;
#pragma unroll
            for (int c = 0; c < 4; c++) {
                float pv = expf(sc[r][c] - mnew);
                sc[r][c] = pv;
                rs += pv;
            }
            lsum[r] = lsum[r] * alpha + rs;
#pragma unroll
            for (int c = 0; c < 4; c++) acc[r][c] *= alpha;
            *(float4*)&p_s[(4 * ty + r) * 64 + 4 * tx] =
                make_float4(sc[r][0], sc[r][1], sc[r][2], sc[r][3]);
        }
        __syncthreads();

#pragma unroll 8
        for (int j = 0; j < 64; j++) {
            float4 vv = *(const float4*)&v_s[j * 64 + tx * 4];
#pragma unroll
            for (int r = 0; r < 4; r++) {
                float pj = p_s[(4 * ty + r) * 64 + j];
                acc[r][0] = fmaf(pj, vv.x, acc[r][0]);
                acc[r][1] = fmaf(pj, vv.y, acc[r][1]);
                acc[r][2] = fmaf(pj, vv.z, acc[r][2]);
                acc[r][3] = fmaf(pj, vv.w, acc[r][3]);
            }
        }
    }

    const int b = bh >> 4, h = bh & 15;
#pragma unroll
    for (int r = 0; r < 4; r++) {
        float l = lsum[r];
#pragma unroll
        for (int o = 8; o > 0; o >>= 1)
            l += __shfl_xor_sync(0xffffffffu, l, o);
        float inv = 1.0f / l;
        int srow = qb * 64 + 4 * ty + r;
        float* dst = g_O + (size_t)(b * NS + srow) * ND + h * 64 + 4 * tx;
        *(float4*)dst = make_float4(acc[r][0] * inv, acc[r][1] * inv,
                                    acc[r][2] * inv, acc[r][3] * inv);
    }
}

// ---------------------------------------------------------------------------
extern "C" void kernel_launch(void* const* d_in, const int* in_sizes, int n_in,
                              void* d_out, int out_size) {
    (void)in_sizes; (void)n_in; (void)out_size;
    const float* x     = (const float*)d_in[0];   // [4,2048,1024]
    const float* W_qkv = (const float*)d_in[1];   // [3,1024,1024] K-major
    const float* W_o   = (const float*)d_in[2];   // [1024,1024]  K-major
    const int*   pos   = (const int*)d_in[3];     // [2048]
    float* out = (float*)d_out;

    const int gemm_smem = 4 * TILE_B;   // 40960 B
    cudaFuncSetAttribute(gemm_mma<0>, cudaFuncAttributeMaxDynamicSharedMemorySize,
                         gemm_smem);
    cudaFuncSetAttribute(gemm_mma<1>, cudaFuncAttributeMaxDynamicSharedMemorySize,
                         gemm_smem);
    cudaFuncSetAttribute(attn_kernel, cudaFuncAttributeMaxDynamicSharedMemorySize,
                         49152);

    // 1) fused QKV projection (bf16x3 HMMA) -> scatter to [b,h,s,dh]
    gemm_mma<0><<<dim3(3072 / 128, NM / 128), 256, gemm_smem>>>(x, W_qkv, nullptr);
    // 2) RoPE in-place on Q and K
    rope_kernel<<<(NB * NH * NS * 32) / 256, 256>>>(pos);
    // 3) causal flash attention -> g_O in [b,s,D] layout
    attn_kernel<<<dim3(NS / 64, NB * NH), 256, 49152>>>();
    // 4) output projection (bf16x3 HMMA)
    gemm_mma<1><<<dim3(ND / 128, NM / 128), 256, gemm_smem>>>(nullptr, W_o, out);
}

// round 10
// speedup vs baseline: 2.3008x; 1.5414x over previous
#include <cuda_runtime.h>
#include <cuda_bf16.h>
#include <math.h>
#include <stdint.h>

#define NB 4
#define NS 2048
#define ND 1024
#define NH 16
#define NDH 64
#define NM (NB * NS)   // 8192

// Scratch (static device globals: allocation-free per harness rules)
__device__ float g_Q[NB * NH * NS * NDH];   // 32 MB, [b,h,s,dh]
__device__ float g_K[NB * NH * NS * NDH];
__device__ float g_V[NB * NH * NS * NDH];
__device__ float g_O[(size_t)NM * ND];      // attention output, [b,s,h*dh+d]

// ===========================================================================
// Helpers
// ===========================================================================
__device__ __forceinline__ uint32_t smem_to_u32(const void* p) {
    uint32_t a;
    asm("{ .reg .u64 t; cvta.to.shared.u64 t, %1; cvt.u32.u64 %0, t; }"
        : "=r"(a) : "l"(p));
    return a;
}
__device__ __forceinline__ uint32_t lds32(uint32_t addr) {
    uint32_t v;
    asm volatile("ld.shared.b32 %0, [%1];" : "=r"(v) : "r"(addr));
    return v;
}
__device__ __forceinline__ void sts64(uint32_t addr, uint2 v) {
    asm volatile("st.shared.v2.b32 [%0], {%1, %2};" :: "r"(addr), "r"(v.x), "r"(v.y)
                 : "memory");
}
__device__ __forceinline__ void sts16(uint32_t addr, uint32_t v) {
    asm volatile("st.shared.b16 [%0], %1;" :: "r"(addr), "r"(v) : "memory");
}

// warp-level bf16 MMA: D(16x8,f32) += A(16x16,bf16 row) * B(16x8,bf16 col)
__device__ __forceinline__ void mma16816(float* c, const uint32_t* a, const uint32_t* b) {
    asm volatile(
        "mma.sync.aligned.m16n8k16.row.col.f32.bf16.bf16.f32 "
        "{%0,%1,%2,%3}, {%4,%5,%6,%7}, {%8,%9}, {%0,%1,%2,%3};"
        : "+f"(c[0]), "+f"(c[1]), "+f"(c[2]), "+f"(c[3])
        : "r"(a[0]), "r"(a[1]), "r"(a[2]), "r"(a[3]), "r"(b[0]), "r"(b[1]));
}

// fp32 -> (bf16 hi, bf16 lo) split of a float4 into packed bf16x2 words.
__device__ __forceinline__ void cvt_split4(float4 v, uint2& h, uint2& l) {
    uint32_t h01, h23, l01, l23;
    asm("cvt.rn.bf16x2.f32 %0, %1, %2;" : "=r"(h01) : "f"(v.y), "f"(v.x));
    asm("cvt.rn.bf16x2.f32 %0, %1, %2;" : "=r"(h23) : "f"(v.w), "f"(v.z));
    float r0 = v.x - __uint_as_float(h01 << 16);
    float r1 = v.y - __uint_as_float(h01 & 0xffff0000u);
    float r2 = v.z - __uint_as_float(h23 << 16);
    float r3 = v.w - __uint_as_float(h23 & 0xffff0000u);
    asm("cvt.rn.bf16x2.f32 %0, %1, %2;" : "=r"(l01) : "f"(r1), "f"(r0));
    asm("cvt.rn.bf16x2.f32 %0, %1, %2;" : "=r"(l23) : "f"(r3), "f"(r2));
    h = make_uint2(h01, h23);
    l = make_uint2(l01, l23);
}
// two floats -> one bf16x2 hi word + one bf16x2 lo (residual) word
__device__ __forceinline__ void pack2_split(float x, float y, uint32_t& h, uint32_t& l) {
    asm("cvt.rn.bf16x2.f32 %0, %1, %2;" : "=r"(h) : "f"(y), "f"(x));
    float rx = x - __uint_as_float(h << 16);
    float ry = y - __uint_as_float(h & 0xffff0000u);
    asm("cvt.rn.bf16x2.f32 %0, %1, %2;" : "=r"(l) : "f"(ry), "f"(rx));
}

// FFMA-only 2^x (degree-6 Taylor on fractional part + exponent stuffing).
// Valid for x <= 0 (clamped at -126); rel err ~2e-5. Avoids the MUFU pipe.
__device__ __forceinline__ float exp2p(float x) {
    x = fmaxf(x, -126.0f);
    float n = floorf(x);
    float f = x - n;
    float p = 0.0001540353f;
    p = fmaf(p, f, 0.0013333558f);
    p = fmaf(p, f, 0.0096181291f);
    p = fmaf(p, f, 0.0555041087f);
    p = fmaf(p, f, 0.2402265070f);
    p = fmaf(p, f, 0.6931471806f);
    p = fmaf(p, f, 1.0f);
    return __int_as_float(__float_as_int(p) + ((int)n << 23));
}

// ===========================================================================
// HMMA GEMM (unchanged from passing R9): C[M,N] = A[M,K] * W[N,K]^T, bf16x3.
// ===========================================================================
#define SROW 80              // smem row stride in bytes (40 bf16)
#define TILE_B (128 * SROW)  // 10240 B per tile

template <int MODE>
__global__ __launch_bounds__(256) void gemm_mma(const float* __restrict__ A,
                                                const float* __restrict__ W,
                                                float* __restrict__ C) {
    constexpr int K = 1024;
    extern __shared__ char smem[];
    const uint32_t sb = smem_to_u32(smem);
    const uint32_t S_AH = sb;
    const uint32_t S_AL = sb + TILE_B;
    const uint32_t S_BH = sb + 2 * TILE_B;
    const uint32_t S_BL = sb + 3 * TILE_B;

    const int tid = threadIdx.x;
    const int wid = tid >> 5, lane = tid & 31;
    const int wm = wid & 1, wn = wid >> 1;
    const int lr = lane >> 2, lc = lane & 3;
    const int m0 = blockIdx.y * 128, n0 = blockIdx.x * 128;
    const float* Ap = ((MODE == 1) ? (const float*)g_O : A) + (size_t)m0 * K;
    const float* Wp = W + (size_t)n0 * K;

    float acc[4][4][4] = {};
    const uint32_t pa = (uint32_t)((wm * 64 + lr) * SROW + lc * 4);
    const uint32_t pb = (uint32_t)((wn * 32 + lr) * SROW + lc * 4);

    for (int kt = 0; kt < K / 32; kt++) {
        float4 av[4], bv[4];
#pragma unroll
        for (int t = 0; t < 4; t++) {
            int idx = tid + t * 256;
            int row = idx >> 3, c4 = idx & 7;
            av[t] = *(const float4*)(Ap + (size_t)row * K + kt * 32 + c4 * 4);
            bv[t] = *(const float4*)(Wp + (size_t)row * K + kt * 32 + c4 * 4);
        }
        __syncthreads();
#pragma unroll
        for (int t = 0; t < 4; t++) {
            int idx = tid + t * 256;
            int row = idx >> 3, c4 = idx & 7;
            uint32_t off = (uint32_t)(row * SROW + c4 * 8);
            uint2 h, l;
            cvt_split4(av[t], h, l);
            sts64(S_AH + off, h);
            sts64(S_AL + off, l);
            cvt_split4(bv[t], h, l);
            sts64(S_BH + off, h);
            sts64(S_BL + off, l);
        }
        __syncthreads();

#pragma unroll
        for (int ks = 0; ks < 2; ks++) {
            const uint32_t ko = ks * 32;
            uint32_t ah[4][4], al[4][4], bh[4][2], bl[4][2];
#pragma unroll
            for (int i = 0; i < 4; i++) {
                uint32_t p = pa + i * (16 * SROW) + ko;
                ah[i][0] = lds32(S_AH + p);
                ah[i][1] = lds32(S_AH + p + 8 * SROW);
                ah[i][2] = lds32(S_AH + p + 16);
                ah[i][3] = lds32(S_AH + p + 8 * SROW + 16);
                al[i][0] = lds32(S_AL + p);
                al[i][1] = lds32(S_AL + p + 8 * SROW);
                al[i][2] = lds32(S_AL + p + 16);
                al[i][3] = lds32(S_AL + p + 8 * SROW + 16);
            }
#pragma unroll
            for (int j = 0; j < 4; j++) {
                uint32_t p = pb + j * (8 * SROW) + ko;
                bh[j][0] = lds32(S_BH + p);
                bh[j][1] = lds32(S_BH + p + 16);
                bl[j][0] = lds32(S_BL + p);
                bl[j][1] = lds32(S_BL + p + 16);
            }
#pragma unroll
            for (int i = 0; i < 4; i++)
#pragma unroll
                for (int j = 0; j < 4; j++) {
                    mma16816(acc[i][j], ah[i], bh[j]);
                    mma16816(acc[i][j], ah[i], bl[j]);
                    mma16816(acc[i][j], al[i], bh[j]);
                }
        }
    }

#pragma unroll
    for (int i = 0; i < 4; i++) {
        int m = m0 + wm * 64 + i * 16 + lr;
#pragma unroll
        for (int j = 0; j < 4; j++) {
            int n = n0 + wn * 32 + j * 8 + lc * 2;
            if (MODE == 0) {
                int kk = n >> 10;
                int o = n & 1023;
                int h = o >> 6, dd = o & 63;
                float* base = (kk == 0) ? g_Q : ((kk == 1) ? g_K : g_V);
                int b = m >> 11, s = m & (NS - 1);
                float* d0 = base + ((size_t)((b * NH + h) * NS + s) << 6) + dd;
                *(float2*)d0 = make_float2(acc[i][j][0], acc[i][j][1]);
                float* d1 = d0 + (8 << 6);
                *(float2*)d1 = make_float2(acc[i][j][2], acc[i][j][3]);
            } else {
                float* d0 = C + (size_t)m * ND + n;
                *(float2*)d0 = make_float2(acc[i][j][0], acc[i][j][1]);
                float* d1 = d0 + (size_t)8 * ND;
                *(float2*)d1 = make_float2(acc[i][j][2], acc[i][j][3]);
            }
        }
    }
}

// ---------------------------------------------------------------------------
// RoPE applied in-place to g_Q and g_K (unchanged).
// ---------------------------------------------------------------------------
__global__ __launch_bounds__(256) void rope_kernel(const int* __restrict__ pos) {
    int idx = blockIdx.x * 256 + threadIdx.x;
    int i = idx & 31;
    int s = (idx >> 5) & (NS - 1);
    float p = (float)pos[s];
    float invf = powf(10000.0f, -(float)i * (1.0f / 32.0f));
    float ang = p * invf;
    float sn, cs;
    sincosf(ang, &sn, &cs);
    float2* q = (float2*)g_Q + idx;
    float2 qv = *q;
    *q = make_float2(qv.x * cs - qv.y * sn, qv.x * sn + qv.y * cs);
    float2* k = (float2*)g_K + idx;
    float2 kv = *k;
    *k = make_float2(kv.x * cs - kv.y * sn, kv.x * sn + kv.y * cs);
}

// ===========================================================================
// Flash attention v2: bf16x3 HMMA for QK^T and P*V, FFMA-poly softmax (base 2).
// 128 threads (4 warps), 64-query tile; warp owns 16 query rows.
// Q frags resident in registers; K [key][dh] and Vt [dh][key] hi/lo in smem,
// row stride 144 B (conflict-free fragment LDS: banks r*36+lc all distinct).
// S-fragment layout == A-fragment layout, so P feeds P*V straight from regs.
// ===========================================================================
#define ASROW 144
#define ATILE (64 * ASROW)   // 9216 B per buffer

__global__ __launch_bounds__(128) void attn_mma() {
    extern __shared__ char smem[];
    const uint32_t sb = smem_to_u32(smem);
    const uint32_t S_KH = sb;
    const uint32_t S_KL = sb + ATILE;
    const uint32_t S_VH = sb + 2 * ATILE;
    const uint32_t S_VL = sb + 3 * ATILE;

    const int tid = threadIdx.x;
    const int wid = tid >> 5, lane = tid & 31;
    const int lr = lane >> 2, lc = lane & 3;
    const int qb = gridDim.x - 1 - blockIdx.x;   // big q-blocks first
    const int bh = blockIdx.y;
    const float* Qp = g_Q + (size_t)bh * NS * NDH;
    const float* Kp = g_K + (size_t)bh * NS * NDH;
    const float* Vp = g_V + (size_t)bh * NS * NDH;

    // ---- stage Q (scaled by 1/sqrt(dh) * log2(e)) into KH/KL, grab frags ----
    const float qscale = 0.1803368867f;   // 0.125 * log2(e)
    {
        float4 qv[8];
#pragma unroll
        for (int t = 0; t < 8; t++) {
            int idx = t * 128 + tid;
            int row = idx >> 4, c4 = idx & 15;
            qv[t] = *(const float4*)(Qp + (size_t)(qb * 64 + row) * 64 + c4 * 4);
        }
#pragma unroll
        for (int t = 0; t < 8; t++) {
            int idx = t * 128 + tid;
            int row = idx >> 4, c4 = idx & 15;
            float4 v = qv[t];
            v.x *= qscale; v.y *= qscale; v.z *= qscale; v.w *= qscale;
            uint2 h, l;
            cvt_split4(v, h, l);
            uint32_t off = (uint32_t)(row * ASROW + c4 * 8);
            sts64(S_KH + off, h);
            sts64(S_KL + off, l);
        }
    }
    __syncthreads();
    uint32_t qh[4][4], ql[4][4];
#pragma unroll
    for (int t = 0; t < 4; t++) {
        uint32_t base = (uint32_t)((wid * 16 + lr) * ASROW + t * 32 + lc * 4);
        qh[t][0] = lds32(S_KH + base);
        qh[t][1] = lds32(S_KH + base + 8 * ASROW);
        qh[t][2] = lds32(S_KH + base + 16);
        qh[t][3] = lds32(S_KH + base + 8 * ASROW + 16);
        ql[t][0] = lds32(S_KL + base);
        ql[t][1] = lds32(S_KL + base + 8 * ASROW);
        ql[t][2] = lds32(S_KL + base + 16);
        ql[t][3] = lds32(S_KL + base + 8 * ASROW + 16);
    }

    float o[8][4] = {};
    float m0 = -1e30f, m1 = -1e30f, l0 = 0.f, l1 = 0.f;

    for (int kb = 0; kb <= qb; kb++) {
        // prefetch K/V tile to registers
        float4 kv4[8], vv4[8];
#pragma unroll
        for (int t = 0; t < 8; t++) {
            int idx = t * 128 + tid;
            int row = idx >> 4, c4 = idx & 15;
            const float* src = Kp + (size_t)(kb * 64 + row) * 64 + c4 * 4;
            kv4[t] = *(const float4*)src;
            vv4[t] = *(const float4*)(src + (Vp - Kp));
        }
        __syncthreads();   // everyone done reading smem from previous iter
#pragma unroll
        for (int t = 0; t < 8; t++) {
            int idx = t * 128 + tid;
            int row = idx >> 4, c4 = idx & 15;
            uint2 h, l;
            cvt_split4(kv4[t], h, l);
            uint32_t off = (uint32_t)(row * ASROW + c4 * 8);
            sts64(S_KH + off, h);
            sts64(S_KL + off, l);
            // V stored transposed [dh][key] as individual bf16
            cvt_split4(vv4[t], h, l);
            uint32_t vo = (uint32_t)((c4 * 4) * ASROW + row * 2);
            sts16(S_VH + vo,             h.x);
            sts16(S_VH + vo + ASROW,     h.x >> 16);
            sts16(S_VH + vo + 2 * ASROW, h.y);
            sts16(S_VH + vo + 3 * ASROW, h.y >> 16);
            sts16(S_VL + vo,             l.x);
            sts16(S_VL + vo + ASROW,     l.x >> 16);
            sts16(S_VL + vo + 2 * ASROW, l.y);
            sts16(S_VL + vo + 3 * ASROW, l.y >> 16);
        }
        __syncthreads();

        // ---- S = Q * K^T (base-2 scaled), 16x64 per warp ----
        float c[8][4] = {};
#pragma unroll
        for (int j = 0; j < 8; j++) {
#pragma unroll
            for (int t = 0; t < 4; t++) {
                uint32_t p = (uint32_t)((8 * j + lr) * ASROW + t * 32 + lc * 4);
                uint32_t bh2[2] = {lds32(S_KH + p), lds32(S_KH + p + 16)};
                uint32_t bl2[2] = {lds32(S_KL + p), lds32(S_KL + p + 16)};
                mma16816(c[j], qh[t], bh2);
                mma16816(c[j], qh[t], bl2);
                mma16816(c[j], ql[t], bh2);
            }
        }

        // ---- causal mask on diagonal tile ----
        if (kb == qb) {
            int qr = wid * 16 + lr;   // local query row (offsets cancel)
#pragma unroll
            for (int j = 0; j < 8; j++) {
                int key = 8 * j + 2 * lc;
                if (key     > qr)     c[j][0] = -1e30f;
                if (key + 1 > qr)     c[j][1] = -1e30f;
                if (key     > qr + 8) c[j][2] = -1e30f;
                if (key + 1 > qr + 8) c[j][3] = -1e30f;
            }
        }

        // ---- online softmax (rows lr and lr+8) ----
        float mx0 = -1e30f, mx1 = -1e30f;
#pragma unroll
        for (int j = 0; j < 8; j++) {
            mx0 = fmaxf(mx0, fmaxf(c[j][0], c[j][1]));
            mx1 = fmaxf(mx1, fmaxf(c[j][2], c[j][3]));
        }
        mx0 = fmaxf(mx0, __shfl_xor_sync(0xffffffffu, mx0, 1));
        mx0 = fmaxf(mx0, __shfl_xor_sync(0xffffffffu, mx0, 2));
        mx1 = fmaxf(mx1, __shfl_xor_sync(0xffffffffu, mx1, 1));
        mx1 = fmaxf(mx1, __shfl_xor_sync(0xffffffffu, mx1, 2));
        float mn0 = fmaxf(m0, mx0), mn1 = fmaxf(m1, mx1);
        float a0 = exp2p(m0 - mn0), a1 = exp2p(m1 - mn1);
        m0 = mn0; m1 = mn1;
        float s0 = 0.f, s1 = 0.f;
#pragma unroll
        for (int j = 0; j < 8; j++) {
            c[j][0] = exp2p(c[j][0] - mn0);
            c[j][1] = exp2p(c[j][1] - mn0);
            c[j][2] = exp2p(c[j][2] - mn1);
            c[j][3] = exp2p(c[j][3] - mn1);
            s0 += c[j][0] + c[j][1];
            s1 += c[j][2] + c[j][3];
        }
        l0 = l0 * a0 + s0;
        l1 = l1 * a1 + s1;
#pragma unroll
        for (int j = 0; j < 8; j++) {
            o[j][0] *= a0; o[j][1] *= a0;
            o[j][2] *= a1; o[j][3] *= a1;
        }

        // ---- P fragments straight from S registers (layout identity) ----
        uint32_t ph[4][4], pl[4][4];
#pragma unroll
        for (int t = 0; t < 4; t++) {
            pack2_split(c[2 * t][0],     c[2 * t][1],     ph[t][0], pl[t][0]);
            pack2_split(c[2 * t][2],     c[2 * t][3],     ph[t][1], pl[t][1]);
            pack2_split(c[2 * t + 1][0], c[2 * t + 1][1], ph[t][2], pl[t][2]);
            pack2_split(c[2 * t + 1][2], c[2 * t + 1][3], ph[t][3], pl[t][3]);
        }

        // ---- O += P * V ----
#pragma unroll
        for (int j = 0; j < 8; j++) {
#pragma unroll
            for (int t = 0; t < 4; t++) {
                uint32_t p = (uint32_t)((8 * j + lr) * ASROW + t * 32 + lc * 4);
                uint32_t vh2[2] = {lds32(S_VH + p), lds32(S_VH + p + 16)};
                uint32_t vl2[2] = {lds32(S_VL + p), lds32(S_VL + p + 16)};
                mma16816(o[j], ph[t], vh2);
                mma16816(o[j], ph[t], vl2);
                mma16816(o[j], pl[t], vh2);
            }
        }
    }

    // ---- epilogue: normalize and write [b,s,D] ----
    l0 += __shfl_xor_sync(0xffffffffu, l0, 1);
    l0 += __shfl_xor_sync(0xffffffffu, l0, 2);
    l1 += __shfl_xor_sync(0xffffffffu, l1, 1);
    l1 += __shfl_xor_sync(0xffffffffu, l1, 2);
    float inv0 = 1.0f / l0, inv1 = 1.0f / l1;
    const int b = bh >> 4, h = bh & 15;
    int qrow = qb * 64 + wid * 16 + lr;
    float* dst = g_O + (size_t)(b * NS + qrow) * ND + h * 64;
#pragma unroll
    for (int j = 0; j < 8; j++) {
        int col = 8 * j + 2 * lc;
        *(float2*)(dst + col) = make_float2(o[j][0] * inv0, o[j][1] * inv0);
        *(float2*)(dst + (size_t)8 * ND + col) =
            make_float2(o[j][2] * inv1, o[j][3] * inv1);
    }
}

// ---------------------------------------------------------------------------
extern "C" void kernel_launch(void* const* d_in, const int* in_sizes, int n_in,
                              void* d_out, int out_size) {
    (void)in_sizes; (void)n_in; (void)out_size;
    const float* x     = (const float*)d_in[0];   // [4,2048,1024]
    const float* W_qkv = (const float*)d_in[1];   // [3,1024,1024] K-major
    const float* W_o   = (const float*)d_in[2];   // [1024,1024]  K-major
    const int*   pos   = (const int*)d_in[3];     // [2048]
    float* out = (float*)d_out;

    const int gemm_smem = 4 * TILE_B;   // 40960 B
    const int attn_smem = 4 * ATILE;    // 36864 B
    cudaFuncSetAttribute(gemm_mma<0>, cudaFuncAttributeMaxDynamicSharedMemorySize,
                         gemm_smem);
    cudaFuncSetAttribute(gemm_mma<1>, cudaFuncAttributeMaxDynamicSharedMemorySize,
                         gemm_smem);
    cudaFuncSetAttribute(attn_mma, cudaFuncAttributeMaxDynamicSharedMemorySize,
                         attn_smem);

    // 1) fused QKV projection (bf16x3 HMMA) -> scatter to [b,h,s,dh]
    gemm_mma<0><<<dim3(3072 / 128, NM / 128), 256, gemm_smem>>>(x, W_qkv, nullptr);
    // 2) RoPE in-place on Q and K
    rope_kernel<<<(NB * NH * NS * 32) / 256, 256>>>(pos);
    // 3) causal flash attention (bf16x3 HMMA + FFMA softmax) -> g_O [b,s,D]
    attn_mma<<<dim3(NS / 64, NB * NH), 128, attn_smem>>>();
    // 4) output projection (bf16x3 HMMA)
    gemm_mma<1><<<dim3(ND / 128, NM / 128), 256, gemm_smem>>>(nullptr, W_o, out);
}

// round 13
// speedup vs baseline: 2.3879x; 1.0378x over previous
#include <cuda_runtime.h>
#include <cuda_bf16.h>
#include <math.h>
#include <stdint.h>

#define NB 4
#define NS 2048
#define ND 1024
#define NH 16
#define NDH 64
#define NM (NB * NS)   // 8192

// Scratch (static device globals: allocation-free per harness rules).
// NOTE: these symbols are ONLY referenced from device code — passing them as
// kernel arguments from host passes the host shadow address (silently readable
// as zeros on GB300 via ATS), which was the R11 correctness bug.
__device__ float g_Q[NB * NH * NS * NDH];   // fp32 [b,h,s,dh] (RoPE + attn)
__device__ float g_K[NB * NH * NS * NDH];
__device__ float g_V[NB * NH * NS * NDH];
__device__ __align__(256) __nv_bfloat16 g_xh[(size_t)NM * ND];
__device__ __align__(256) __nv_bfloat16 g_xl[(size_t)NM * ND];
__device__ __align__(256) __nv_bfloat16 g_wh[(size_t)4096 * 1024];  // qkv 0..3071, wo 3072..4095
__device__ __align__(256) __nv_bfloat16 g_wl[(size_t)4096 * 1024];
__device__ __align__(256) __nv_bfloat16 g_oh[(size_t)NM * ND];      // attn out hi/lo
__device__ __align__(256) __nv_bfloat16 g_ol[(size_t)NM * ND];

// ===========================================================================
// Helpers
// ===========================================================================
__device__ __forceinline__ uint32_t smem_to_u32(const void* p) {
    uint32_t a;
    asm("{ .reg .u64 t; cvta.to.shared.u64 t, %1; cvt.u32.u64 %0, t; }"
        : "=r"(a) : "l"(p));
    return a;
}
__device__ __forceinline__ uint32_t lds32(uint32_t addr) {
    uint32_t v;
    asm volatile("ld.shared.b32 %0, [%1];" : "=r"(v) : "r"(addr));
    return v;
}
__device__ __forceinline__ void sts64(uint32_t addr, uint2 v) {
    asm volatile("st.shared.v2.b32 [%0], {%1, %2};" :: "r"(addr), "r"(v.x), "r"(v.y)
                 : "memory");
}
__device__ __forceinline__ void sts16(uint32_t addr, uint32_t v) {
    asm volatile("st.shared.b16 [%0], %1;" :: "r"(addr), "r"(v) : "memory");
}
__device__ __forceinline__ void cpa16(uint32_t saddr, const void* g) {
    asm volatile("cp.async.cg.shared.global [%0], [%1], 16;"
                 :: "r"(saddr), "l"(g) : "memory");
}
#define CP_COMMIT() asm volatile("cp.async.commit_group;" ::: "memory")
#define CP_WAIT(n)  asm volatile("cp.async.wait_group %0;" :: "n"(n) : "memory")
__device__ __forceinline__ void ldsm4(uint32_t* r, uint32_t a) {
    asm volatile("ldmatrix.sync.aligned.m8n8.x4.shared.b16 {%0,%1,%2,%3}, [%4];"
                 : "=r"(r[0]), "=r"(r[1]), "=r"(r[2]), "=r"(r[3]) : "r"(a));
}

// warp-level bf16 MMA: D(16x8,f32) += A(16x16,bf16 row) * B(16x8,bf16 col)
__device__ __forceinline__ void mma16816(float* c, const uint32_t* a, const uint32_t* b) {
    asm volatile(
        "mma.sync.aligned.m16n8k16.row.col.f32.bf16.bf16.f32 "
        "{%0,%1,%2,%3}, {%4,%5,%6,%7}, {%8,%9}, {%0,%1,%2,%3};"
        : "+f"(c[0]), "+f"(c[1]), "+f"(c[2]), "+f"(c[3])
        : "r"(a[0]), "r"(a[1]), "r"(a[2]), "r"(a[3]), "r"(b[0]), "r"(b[1]));
}

// fp32 -> (bf16 hi, bf16 lo) split of a float4 into packed bf16x2 words.
__device__ __forceinline__ void cvt_split4(float4 v, uint2& h, uint2& l) {
    uint32_t h01, h23, l01, l23;
    asm("cvt.rn.bf16x2.f32 %0, %1, %2;" : "=r"(h01) : "f"(v.y), "f"(v.x));
    asm("cvt.rn.bf16x2.f32 %0, %1, %2;" : "=r"(h23) : "f"(v.w), "f"(v.z));
    float r0 = v.x - __uint_as_float(h01 << 16);
    float r1 = v.y - __uint_as_float(h01 & 0xffff0000u);
    float r2 = v.z - __uint_as_float(h23 << 16);
    float r3 = v.w - __uint_as_float(h23 & 0xffff0000u);
    asm("cvt.rn.bf16x2.f32 %0, %1, %2;" : "=r"(l01) : "f"(r1), "f"(r0));
    asm("cvt.rn.bf16x2.f32 %0, %1, %2;" : "=r"(l23) : "f"(r3), "f"(r2));
    h = make_uint2(h01, h23);
    l = make_uint2(l01, l23);
}
__device__ __forceinline__ void pack2_split(float x, float y, uint32_t& h, uint32_t& l) {
    asm("cvt.rn.bf16x2.f32 %0, %1, %2;" : "=r"(h) : "f"(y), "f"(x));
    float rx = x - __uint_as_float(h << 16);
    float ry = y - __uint_as_float(h & 0xffff0000u);
    asm("cvt.rn.bf16x2.f32 %0, %1, %2;" : "=r"(l) : "f"(ry), "f"(rx));
}

// FFMA-only 2^x (x <= 0, clamped at -126); rel err ~2e-5. Avoids the MUFU pipe.
__device__ __forceinline__ float exp2p(float x) {
    x = fmaxf(x, -126.0f);
    float n = floorf(x);
    float f = x - n;
    float p = 0.0001540353f;
    p = fmaf(p, f, 0.0013333558f);
    p = fmaf(p, f, 0.0096181291f);
    p = fmaf(p, f, 0.0555041087f);
    p = fmaf(p, f, 0.2402265070f);
    p = fmaf(p, f, 0.6931471806f);
    p = fmaf(p, f, 1.0f);
    return __int_as_float(__float_as_int(p) + ((int)n << 23));
}

// ---------------------------------------------------------------------------
// Convert: fp32 -> bf16 hi/lo. Destination selected by template IN DEVICE CODE
// (device-global addresses must never be passed from host).
// DST 0: g_xh/g_xl; DST 1: g_wh/g_wl (+0); DST 2: g_wh/g_wl (+3072*1024).
// ---------------------------------------------------------------------------
template <int DST>
__global__ __launch_bounds__(256) void cvt_kernel(const float4* __restrict__ src,
                                                  int n4) {
    int i = blockIdx.x * 256 + threadIdx.x;
    if (i >= n4) return;
    uint2 *hi, *lo;
    if (DST == 0) { hi = (uint2*)g_xh; lo = (uint2*)g_xl; }
    else if (DST == 1) { hi = (uint2*)g_wh; lo = (uint2*)g_wl; }
    else {
        hi = (uint2*)(g_wh + (size_t)3072 * 1024);
        lo = (uint2*)(g_wl + (size_t)3072 * 1024);
    }
    uint2 h, l;
    cvt_split4(src[i], h, l);
    hi[i] = h;
    lo[i] = l;
}

// ===========================================================================
// GEMM: C[M,N] = A[M,K]*B[N,K]^T, pre-split bf16 hi/lo operands (device
// globals selected by MODE in device code). 128x128 tile, BK=32, 256 threads,
// cp.async 2-stage pipeline + ldmatrix.x4 fragments, XOR-swizzled smem.
// MODE 0: A=g_xh/xl, B=g_wh/wl; scatter to g_Q/g_K/g_V.
// MODE 1: A=g_oh/ol, B=g_wh/wl+3072*1024; write C.
// ===========================================================================
#define GST 32768   // stage stride (4 arrays x 8192 B)

__device__ __forceinline__ uint32_t swz(int r, int c) {
    // 8KB array: row r (0..127) of 64B, chunk c (0..3) of 16B, XOR swizzle
    return (uint32_t)((r >> 1) * 128 + ((((r & 1) * 4 + c) ^ ((r >> 1) & 7)) * 16));
}

template <int MODE>
__global__ __launch_bounds__(256) void gemm_bf16(float* __restrict__ C) {
    constexpr int K = 1024;
    extern __shared__ char smem[];
    const uint32_t sb = smem_to_u32(smem);

    const __nv_bfloat16* Ah = (MODE == 0) ? g_xh : g_oh;
    const __nv_bfloat16* Al = (MODE == 0) ? g_xl : g_ol;
    const __nv_bfloat16* Bh = (MODE == 0) ? g_wh : (g_wh + (size_t)3072 * 1024);
    const __nv_bfloat16* Bl = (MODE == 0) ? g_wl : (g_wl + (size_t)3072 * 1024);

    const int tid = threadIdx.x;
    const int wid = tid >> 5, lane = tid & 31;
    const int wm = wid & 1, wn = wid >> 1;
    const int lr = lane >> 2, lc = lane & 3;
    const int m0 = blockIdx.y * 128, n0 = blockIdx.x * 128;

    const int cr = tid >> 1;            // copy row 0..127
    const int cc0 = (tid & 1) * 2;      // chunk 0 or 2 (+u)
    const __nv_bfloat16* gAh = Ah + (size_t)(m0 + cr) * K;
    const __nv_bfloat16* gAl = Al + (size_t)(m0 + cr) * K;
    const __nv_bfloat16* gBh = Bh + (size_t)(n0 + cr) * K;
    const __nv_bfloat16* gBl = Bl + (size_t)(n0 + cr) * K;

#define ISSUE(kt, st)                                                          \
    {                                                                          \
        uint32_t bse = sb + (st) * GST;                                        \
        int kb = (kt) * 32;                                                    \
        _Pragma("unroll") for (int u = 0; u < 2; u++) {                        \
            int c = cc0 + u;                                                   \
            uint32_t o = swz(cr, c);                                           \
            cpa16(bse + o, gAh + kb + c * 8);                                  \
            cpa16(bse + 8192 + o, gAl + kb + c * 8);                           \
            cpa16(bse + 16384 + o, gBh + kb + c * 8);                          \
            cpa16(bse + 24576 + o, gBl + kb + c * 8);                          \
        }                                                                      \
        CP_COMMIT();                                                           \
    }

    float acc[4][4][4] = {};

    ISSUE(0, 0);
    for (int kt = 0; kt < K / 32; kt++) {
        if (kt + 1 < K / 32) {
            ISSUE(kt + 1, (kt + 1) & 1);
            CP_WAIT(1);
        } else {
            CP_WAIT(0);
        }
        __syncthreads();

        const uint32_t stage = sb + (kt & 1) * GST;
#pragma unroll
        for (int ks = 0; ks < 2; ks++) {
            uint32_t ah[4][4], al[4][4];
#pragma unroll
            for (int i = 0; i < 4; i++) {
                int r = wm * 64 + i * 16 + (lane & 15);
                int c = 2 * ks + (lane >> 4);
                uint32_t o = swz(r, c);
                ldsm4(ah[i], stage + o);
                ldsm4(al[i], stage + 8192 + o);
            }
            uint32_t bh[4][2], bl[4][2];
#pragma unroll
            for (int jp = 0; jp < 2; jp++) {
                int n = wn * 32 + jp * 16 + ((lane >> 4) & 1) * 8 + (lane & 7);
                int c = 2 * ks + ((lane >> 3) & 1);
                uint32_t o = swz(n, c);
                uint32_t t[4];
                ldsm4(t, stage + 16384 + o);
                bh[2 * jp][0] = t[0]; bh[2 * jp][1] = t[1];
                bh[2 * jp + 1][0] = t[2]; bh[2 * jp + 1][1] = t[3];
                ldsm4(t, stage + 24576 + o);
                bl[2 * jp][0] = t[0]; bl[2 * jp][1] = t[1];
                bl[2 * jp + 1][0] = t[2]; bl[2 * jp + 1][1] = t[3];
            }
#pragma unroll
            for (int i = 0; i < 4; i++)
#pragma unroll
                for (int j = 0; j < 4; j++) {
                    mma16816(acc[i][j], ah[i], bh[j]);
                    mma16816(acc[i][j], ah[i], bl[j]);
                    mma16816(acc[i][j], al[i], bh[j]);
                }
        }
        __syncthreads();
    }

    // Epilogue (layout verified in R9/R10 passing kernels)
#pragma unroll
    for (int i = 0; i < 4; i++) {
        int m = m0 + wm * 64 + i * 16 + lr;
#pragma unroll
        for (int j = 0; j < 4; j++) {
            int n = n0 + wn * 32 + j * 8 + lc * 2;
            if (MODE == 0) {
                int kk = n >> 10;
                int o = n & 1023;
                int h = o >> 6, dd = o & 63;
                float* base = (kk == 0) ? g_Q : ((kk == 1) ? g_K : g_V);
                int b = m >> 11, s = m & (NS - 1);
                float* d0 = base + ((size_t)((b * NH + h) * NS + s) << 6) + dd;
                *(float2*)d0 = make_float2(acc[i][j][0], acc[i][j][1]);
                float* d1 = d0 + (8 << 6);
                *(float2*)d1 = make_float2(acc[i][j][2], acc[i][j][3]);
            } else {
                float* d0 = C + (size_t)m * ND + n;
                *(float2*)d0 = make_float2(acc[i][j][0], acc[i][j][1]);
                float* d1 = d0 + (size_t)8 * ND;
                *(float2*)d1 = make_float2(acc[i][j][2], acc[i][j][3]);
            }
        }
    }
#undef ISSUE
}

// ---------------------------------------------------------------------------
// RoPE applied in-place to g_Q and g_K (unchanged).
// ---------------------------------------------------------------------------
__global__ __launch_bounds__(256) void rope_kernel(const int* __restrict__ pos) {
    int idx = blockIdx.x * 256 + threadIdx.x;
    int i = idx & 31;
    int s = (idx >> 5) & (NS - 1);
    float p = (float)pos[s];
    float invf = powf(10000.0f, -(float)i * (1.0f / 32.0f));
    float ang = p * invf;
    float sn, cs;
    sincosf(ang, &sn, &cs);
    float2* q = (float2*)g_Q + idx;
    float2 qv = *q;
    *q = make_float2(qv.x * cs - qv.y * sn, qv.x * sn + qv.y * cs);
    float2* k = (float2*)g_K + idx;
    float2 kv = *k;
    *k = make_float2(kv.x * cs - kv.y * sn, kv.x * sn + kv.y * cs);
}

// ===========================================================================
// Flash attention (R10 winner; epilogue writes bf16 hi/lo into g_oh/g_ol).
// ===========================================================================
#define ASROW 144
#define ATILE (64 * ASROW)   // 9216 B per buffer

__global__ __launch_bounds__(128) void attn_mma() {
    extern __shared__ char smem[];
    const uint32_t sb = smem_to_u32(smem);
    const uint32_t S_KH = sb;
    const uint32_t S_KL = sb + ATILE;
    const uint32_t S_VH = sb + 2 * ATILE;
    const uint32_t S_VL = sb + 3 * ATILE;

    const int tid = threadIdx.x;
    const int wid = tid >> 5, lane = tid & 31;
    const int lr = lane >> 2, lc = lane & 3;
    const int qb = gridDim.x - 1 - blockIdx.x;
    const int bh = blockIdx.y;
    const float* Qp = g_Q + (size_t)bh * NS * NDH;
    const float* Kp = g_K + (size_t)bh * NS * NDH;
    const float* Vp = g_V + (size_t)bh * NS * NDH;

    const float qscale = 0.1803368867f;   // 0.125 * log2(e)
    {
        float4 qv[8];
#pragma unroll
        for (int t = 0; t < 8; t++) {
            int idx = t * 128 + tid;
            int row = idx >> 4, c4 = idx & 15;
            qv[t] = *(const float4*)(Qp + (size_t)(qb * 64 + row) * 64 + c4 * 4);
        }
#pragma unroll
        for (int t = 0; t < 8; t++) {
            int idx = t * 128 + tid;
            int row = idx >> 4, c4 = idx & 15;
            float4 v = qv[t];
            v.x *= qscale; v.y *= qscale; v.z *= qscale; v.w *= qscale;
            uint2 h, l;
            cvt_split4(v, h, l);
            uint32_t off = (uint32_t)(row * ASROW + c4 * 8);
            sts64(S_KH + off, h);
            sts64(S_KL + off, l);
        }
    }
    __syncthreads();
    uint32_t qh[4][4], ql[4][4];
#pragma unroll
    for (int t = 0; t < 4; t++) {
        uint32_t base = (uint32_t)((wid * 16 + lr) * ASROW + t * 32 + lc * 4);
        qh[t][0] = lds32(S_KH + base);
        qh[t][1] = lds32(S_KH + base + 8 * ASROW);
        qh[t][2] = lds32(S_KH + base + 16);
        qh[t][3] = lds32(S_KH + base + 8 * ASROW + 16);
        ql[t][0] = lds32(S_KL + base);
        ql[t][1] = lds32(S_KL + base + 8 * ASROW);
        ql[t][2] = lds32(S_KL + base + 16);
        ql[t][3] = lds32(S_KL + base + 8 * ASROW + 16);
    }

    float o[8][4] = {};
    float m0 = -1e30f, m1 = -1e30f, l0 = 0.f, l1 = 0.f;

    for (int kb = 0; kb <= qb; kb++) {
        float4 kv4[8], vv4[8];
#pragma unroll
        for (int t = 0; t < 8; t++) {
            int idx = t * 128 + tid;
            int row = idx >> 4, c4 = idx & 15;
            const float* src = Kp + (size_t)(kb * 64 + row) * 64 + c4 * 4;
            kv4[t] = *(const float4*)src;
            vv4[t] = *(const float4*)(src + (Vp - Kp));
        }
        __syncthreads();
#pragma unroll
        for (int t = 0; t < 8; t++) {
            int idx = t * 128 + tid;
            int row = idx >> 4, c4 = idx & 15;
            uint2 h, l;
            cvt_split4(kv4[t], h, l);
            uint32_t off = (uint32_t)(row * ASROW + c4 * 8);
            sts64(S_KH + off, h);
            sts64(S_KL + off, l);
            cvt_split4(vv4[t], h, l);
            uint32_t vo = (uint32_t)((c4 * 4) * ASROW + row * 2);
            sts16(S_VH + vo,             h.x);
            sts16(S_VH + vo + ASROW,     h.x >> 16);
            sts16(S_VH + vo + 2 * ASROW, h.y);
            sts16(S_VH + vo + 3 * ASROW, h.y >> 16);
            sts16(S_VL + vo,             l.x);
            sts16(S_VL + vo + ASROW,     l.x >> 16);
            sts16(S_VL + vo + 2 * ASROW, l.y);
            sts16(S_VL + vo + 3 * ASROW, l.y >> 16);
        }
        __syncthreads();

        float c[8][4] = {};
#pragma unroll
        for (int j = 0; j < 8; j++) {
#pragma unroll
            for (int t = 0; t < 4; t++) {
                uint32_t p = (uint32_t)((8 * j + lr) * ASROW + t * 32 + lc * 4);
                uint32_t bh2[2] = {lds32(S_KH + p), lds32(S_KH + p + 16)};
                uint32_t bl2[2] = {lds32(S_KL + p), lds32(S_KL + p + 16)};
                mma16816(c[j], qh[t], bh2);
                mma16816(c[j], qh[t], bl2);
                mma16816(c[j], ql[t], bh2);
            }
        }

        if (kb == qb) {
            int qr = wid * 16 + lr;
#pragma unroll
            for (int j = 0; j < 8; j++) {
                int key = 8 * j + 2 * lc;
                if (key     > qr)     c[j][0] = -1e30f;
                if (key + 1 > qr)     c[j][1] = -1e30f;
                if (key     > qr + 8) c[j][2] = -1e30f;
                if (key + 1 > qr + 8) c[j][3] = -1e30f;
            }
        }

        float mx0 = -1e30f, mx1 = -1e30f;
#pragma unroll
        for (int j = 0; j < 8; j++) {
            mx0 = fmaxf(mx0, fmaxf(c[j][0], c[j][1]));
            mx1 = fmaxf(mx1, fmaxf(c[j][2], c[j][3]));
        }
        mx0 = fmaxf(mx0, __shfl_xor_sync(0xffffffffu, mx0, 1));
        mx0 = fmaxf(mx0, __shfl_xor_sync(0xffffffffu, mx0, 2));
        mx1 = fmaxf(mx1, __shfl_xor_sync(0xffffffffu, mx1, 1));
        mx1 = fmaxf(mx1, __shfl_xor_sync(0xffffffffu, mx1, 2));
        float mn0 = fmaxf(m0, mx0), mn1 = fmaxf(m1, mx1);
        float a0 = exp2p(m0 - mn0), a1 = exp2p(m1 - mn1);
        m0 = mn0; m1 = mn1;
        float s0 = 0.f, s1 = 0.f;
#pragma unroll
        for (int j = 0; j < 8; j++) {
            c[j][0] = exp2p(c[j][0] - mn0);
            c[j][1] = exp2p(c[j][1] - mn0);
            c[j][2] = exp2p(c[j][2] - mn1);
            c[j][3] = exp2p(c[j][3] - mn1);
            s0 += c[j][0] + c[j][1];
            s1 += c[j][2] + c[j][3];
        }
        l0 = l0 * a0 + s0;
        l1 = l1 * a1 + s1;
#pragma unroll
        for (int j = 0; j < 8; j++) {
            o[j][0] *= a0; o[j][1] *= a0;
            o[j][2] *= a1; o[j][3] *= a1;
        }

        uint32_t ph[4][4], pl[4][4];
#pragma unroll
        for (int t = 0; t < 4; t++) {
            pack2_split(c[2 * t][0],     c[2 * t][1],     ph[t][0], pl[t][0]);
            pack2_split(c[2 * t][2],     c[2 * t][3],     ph[t][1], pl[t][1]);
            pack2_split(c[2 * t + 1][0], c[2 * t + 1][1], ph[t][2], pl[t][2]);
            pack2_split(c[2 * t + 1][2], c[2 * t + 1][3], ph[t][3], pl[t][3]);
        }

#pragma unroll
        for (int j = 0; j < 8; j++) {
#pragma unroll
            for (int t = 0; t < 4; t++) {
                uint32_t p = (uint32_t)((8 * j + lr) * ASROW + t * 32 + lc * 4);
                uint32_t vh2[2] = {lds32(S_VH + p), lds32(S_VH + p + 16)};
                uint32_t vl2[2] = {lds32(S_VL + p), lds32(S_VL + p + 16)};
                mma16816(o[j], ph[t], vh2);
                mma16816(o[j], ph[t], vl2);
                mma16816(o[j], pl[t], vh2);
            }
        }
    }

    // epilogue: normalize, pack bf16 hi/lo, write g_oh/g_ol [m][d/2]
    l0 += __shfl_xor_sync(0xffffffffu, l0, 1);
    l0 += __shfl_xor_sync(0xffffffffu, l0, 2);
    l1 += __shfl_xor_sync(0xffffffffu, l1, 1);
    l1 += __shfl_xor_sync(0xffffffffu, l1, 2);
    float inv0 = 1.0f / l0, inv1 = 1.0f / l1;
    const int b = bh >> 4, h = bh & 15;
    int m = b * NS + qb * 64 + wid * 16 + lr;
    uint32_t* oh = (uint32_t*)g_oh;
    uint32_t* ol = (uint32_t*)g_ol;
#pragma unroll
    for (int j = 0; j < 8; j++) {
        int w = h * 32 + 4 * j + lc;
        uint32_t hh, ll;
        pack2_split(o[j][0] * inv0, o[j][1] * inv0, hh, ll);
        oh[(size_t)m * 512 + w] = hh;
        ol[(size_t)m * 512 + w] = ll;
        pack2_split(o[j][2] * inv1, o[j][3] * inv1, hh, ll);
        oh[(size_t)(m + 8) * 512 + w] = hh;
        ol[(size_t)(m + 8) * 512 + w] = ll;
    }
}

// ---------------------------------------------------------------------------
extern "C" void kernel_launch(void* const* d_in, const int* in_sizes, int n_in,
                              void* d_out, int out_size) {
    (void)in_sizes; (void)n_in; (void)out_size;
    const float* x     = (const float*)d_in[0];   // [4,2048,1024]
    const float* W_qkv = (const float*)d_in[1];   // [3,1024,1024] K-major
    const float* W_o   = (const float*)d_in[2];   // [1024,1024]  K-major
    const int*   pos   = (const int*)d_in[3];     // [2048]
    float* out = (float*)d_out;

    const int gemm_smem = 2 * GST;      // 65536 B
    const int attn_smem = 4 * ATILE;    // 36864 B
    cudaFuncSetAttribute(gemm_bf16<0>, cudaFuncAttributeMaxDynamicSharedMemorySize,
                         gemm_smem);
    cudaFuncSetAttribute(gemm_bf16<1>, cudaFuncAttributeMaxDynamicSharedMemorySize,
                         gemm_smem);
    cudaFuncSetAttribute(attn_mma, cudaFuncAttributeMaxDynamicSharedMemorySize,
                         attn_smem);

    // 0) one-shot bf16 hi/lo splits (outputs selected in device code)
    cvt_kernel<0><<<(NM * ND / 4) / 256, 256>>>((const float4*)x, NM * ND / 4);
    cvt_kernel<1><<<(3 * 1024 * 1024 / 4) / 256, 256>>>((const float4*)W_qkv,
                                                        3 * 1024 * 1024 / 4);
    cvt_kernel<2><<<(1024 * 1024 / 4) / 256, 256>>>((const float4*)W_o,
                                                    1024 * 1024 / 4);

    // 1) fused QKV projection (cp.async + ldmatrix HMMA) -> g_Q/g_K/g_V
    gemm_bf16<0><<<dim3(3072 / 128, NM / 128), 256, gemm_smem>>>(nullptr);
    // 2) RoPE in-place on Q and K
    rope_kernel<<<(NB * NH * NS * 32) / 256, 256>>>(pos);
    // 3) causal flash attention -> g_oh/g_ol (bf16 hi/lo, [b,s,D])
    attn_mma<<<dim3(NS / 64, NB * NH), 128, attn_smem>>>();
    // 4) output projection
    gemm_bf16<1><<<dim3(ND / 128, NM / 128), 256, gemm_smem>>>(out);
}